// round 2
// baseline (speedup 1.0000x reference)
#include <cuda_runtime.h>
#include <cstddef>

#define H 256
#define NCAP 100000
#define BCAP 256
#define BN_EPS 1e-5f

// ---------------- scratch (static __device__, allocation-free) ----------------
__device__ float g_bufA[(size_t)NCAP * H];   // GEMM output h
__device__ float g_bufB[(size_t)NCAP * H];   // scatter accumulator (kept zeroed)
__device__ float g_bufC[(size_t)NCAP * H];   // h1 (residual)
__device__ float g_deg[NCAP];
__device__ float g_dinv[NCAP];
__device__ float g_cnt[BCAP];
__device__ float g_pool[BCAP * H];
__device__ float g_emb[BCAP * H];
__device__ float g_z1[BCAP * 256];
__device__ float g_z2[BCAP * 128];

// vectorized fp32 reduction (no return) — sm_90+ PTX
__device__ __forceinline__ void red_add_v4(float* addr, float x, float y, float z, float w) {
    asm volatile("red.global.add.v4.f32 [%0], {%1, %2, %3, %4};"
                 :: "l"(addr), "f"(x), "f"(y), "f"(z), "f"(w) : "memory");
}

// ---------------- zero small accumulators (deg, cnt, pool) ----------------
__global__ void k_zero(int n_nodes, int nb) {
    int total = n_nodes + nb + nb * H;
    for (int i = blockIdx.x * blockDim.x + threadIdx.x; i < total;
         i += gridDim.x * blockDim.x) {
        if (i < n_nodes) g_deg[i] = 0.f;
        else if (i < n_nodes + nb) g_cnt[i - n_nodes] = 0.f;
        else g_pool[i - n_nodes - nb] = 0.f;
    }
}

// ---------------- degree accumulation ----------------
__global__ void k_deg(const int* __restrict__ dst, const float* __restrict__ ew, int E) {
    for (int e = blockIdx.x * blockDim.x + threadIdx.x; e < E;
         e += gridDim.x * blockDim.x)
        atomicAdd(&g_deg[dst[e]], ew[e]);
}

// ---------------- dinv + per-graph node counts ----------------
__global__ void k_prep(const int* __restrict__ batch, int n_nodes) {
    for (int i = blockIdx.x * blockDim.x + threadIdx.x; i < n_nodes;
         i += gridDim.x * blockDim.x) {
        g_dinv[i] = rsqrtf(g_deg[i] + 1.0f);
        atomicAdd(&g_cnt[batch[i]], 1.0f);
    }
}

// ---------------- fp32 tiled GEMM: C[M,Nc] = A[M,K] @ W[K,Nc] ----------------
// 64x64 tile, BK=16, 256 threads, 4x4 per thread.
__global__ void k_gemm(const float* __restrict__ A, const float* __restrict__ W,
                       float* __restrict__ C, int M, int K, int Nc) {
    __shared__ float As[16][68];   // transposed, padded
    __shared__ float Bs[16][64];

    int t = threadIdx.x;
    int tx = t & 15, ty = t >> 4;
    int row0 = blockIdx.y * 64;
    int col0 = blockIdx.x * 64;

    int arow = t >> 2;          // 0..63
    int akq  = (t & 3) * 4;     // 0,4,8,12
    int brow = t >> 4;          // 0..15
    int bc   = (t & 15) * 4;    // 0..60

    float acc[4][4] = {};

    for (int k0 = 0; k0 < K; k0 += 16) {
        float4 av = make_float4(0.f, 0.f, 0.f, 0.f);
        int gr = row0 + arow;
        if (gr < M)
            av = *(const float4*)(A + (size_t)gr * K + k0 + akq);
        As[akq + 0][arow] = av.x;
        As[akq + 1][arow] = av.y;
        As[akq + 2][arow] = av.z;
        As[akq + 3][arow] = av.w;

        float4 bv = *(const float4*)(W + (size_t)(k0 + brow) * Nc + col0 + bc);
        *(float4*)&Bs[brow][bc] = bv;
        __syncthreads();

        #pragma unroll
        for (int k = 0; k < 16; k++) {
            float4 a4 = *(const float4*)&As[k][ty * 4];
            float4 b4 = *(const float4*)&Bs[k][tx * 4];
            float a[4] = {a4.x, a4.y, a4.z, a4.w};
            float b[4] = {b4.x, b4.y, b4.z, b4.w};
            #pragma unroll
            for (int i = 0; i < 4; i++)
                #pragma unroll
                for (int j = 0; j < 4; j++)
                    acc[i][j] += a[i] * b[j];
        }
        __syncthreads();
    }

    #pragma unroll
    for (int i = 0; i < 4; i++) {
        int gr = row0 + ty * 4 + i;
        if (gr < M) {
            float4 o = make_float4(acc[i][0], acc[i][1], acc[i][2], acc[i][3]);
            *(float4*)(C + (size_t)gr * Nc + col0 + tx * 4) = o;
        }
    }
}

// ---------------- edge scatter: g_bufB[dst] += h[src] * norm ----------------
// 64 threads per edge, one float4 load + one red.v4 per thread.
__global__ void k_scatter(const float* __restrict__ h, const int* __restrict__ src,
                          const int* __restrict__ dst, const float* __restrict__ ew,
                          int E) {
    int lane = threadIdx.x & 63;
    int eg = blockIdx.x * 4 + (threadIdx.x >> 6);
    int stride = gridDim.x * 4;
    for (int e = eg; e < E; e += stride) {
        int s = __ldg(src + e), d = __ldg(dst + e);
        float nrm = __ldg(&g_dinv[s]) * __ldg(ew + e) * __ldg(&g_dinv[d]);
        float4 v = *(const float4*)(h + (size_t)s * H + lane * 4);
        red_add_v4(&g_bufB[(size_t)d * H + lane * 4],
                   v.x * nrm, v.y * nrm, v.z * nrm, v.w * nrm);
    }
}

// ---------------- layer 1 finalize: out = relu(bn(agg + h*dinv^2 + b)) ----------------
// also re-zeroes g_bufB for the next scatter.
__global__ void k_final1(const float* __restrict__ h, float* __restrict__ out,
                         const float* __restrict__ bb, const float* __restrict__ gg,
                         const float* __restrict__ be, const float* __restrict__ rm,
                         const float* __restrict__ rv) {
    int n = blockIdx.x, c = threadIdx.x;
    size_t idx = (size_t)n * H + c;
    float di = g_dinv[n];
    float v = g_bufB[idx] + h[idx] * di * di + bb[c];
    v = (v - rm[c]) * rsqrtf(rv[c] + BN_EPS) * gg[c] + be[c];
    out[idx] = fmaxf(v, 0.f);
    g_bufB[idx] = 0.f;
}

// ---------------- layer 2 finalize + residual + mean-pool accumulate ----------------
__global__ void k_final2(const float* __restrict__ h, const float* __restrict__ res,
                         const int* __restrict__ batch,
                         const float* __restrict__ bb, const float* __restrict__ gg,
                         const float* __restrict__ be, const float* __restrict__ rm,
                         const float* __restrict__ rv) {
    int n = blockIdx.x, c = threadIdx.x;
    size_t idx = (size_t)n * H + c;
    float di = g_dinv[n];
    float v = g_bufB[idx] + h[idx] * di * di + bb[c];
    v = (v - rm[c]) * rsqrtf(rv[c] + BN_EPS) * gg[c] + be[c];
    v = fmaxf(v, 0.f) + res[idx];
    atomicAdd(&g_pool[(size_t)batch[n] * H + c], v);
    g_bufB[idx] = 0.f;
}

// ---------------- per-graph mean + write emb output ----------------
__global__ void k_emb(float* __restrict__ out, int out_size, int nb) {
    int i = blockIdx.x * blockDim.x + threadIdx.x;
    if (i < nb * H) {
        int b = i >> 8;
        float e = g_pool[i] / fmaxf(g_cnt[b], 1.0f);
        g_emb[i] = e;
        if (out_size >= nb * 2 + nb * H)
            out[nb * 2 + i] = e;
    }
}

// ---------------- classifier MLP layer: out = relu(bn(in @ W + b)) ----------------
__global__ void k_mlp(const float* __restrict__ in, const float* __restrict__ W,
                      const float* __restrict__ bb, const float* __restrict__ gg,
                      const float* __restrict__ be, const float* __restrict__ rm,
                      const float* __restrict__ rv, float* __restrict__ out,
                      int Kin, int Nout) {
    extern __shared__ float sh[];
    int b = blockIdx.x, t = threadIdx.x;
    for (int k = t; k < Kin; k += blockDim.x) sh[k] = in[(size_t)b * Kin + k];
    __syncthreads();
    if (t < Nout) {
        float acc = 0.f;
        for (int k = 0; k < Kin; k++) acc += sh[k] * W[(size_t)k * Nout + t];
        acc += bb[t];
        acc = (acc - rm[t]) * rsqrtf(rv[t] + BN_EPS) * gg[t] + be[t];
        out[(size_t)b * Nout + t] = fmaxf(acc, 0.f);
    }
}

// ---------------- final logits ----------------
__global__ void k_logits(const float* __restrict__ W, const float* __restrict__ bb,
                         float* __restrict__ out, int nb) {
    int i = blockIdx.x * blockDim.x + threadIdx.x;
    if (i < nb * 2) {
        int b = i >> 1, o = i & 1;
        float acc = bb[o];
        for (int k = 0; k < 128; k++) acc += g_z2[b * 128 + k] * W[k * 2 + o];
        out[i] = acc;
    }
}

extern "C" void kernel_launch(void* const* d_in, const int* in_sizes, int n_in,
                              void* d_out, int out_size) {
    const float* x     = (const float*)d_in[0];
    const int*   ei    = (const int*)d_in[1];
    const float* ew    = (const float*)d_in[2];
    const int*   batch = (const int*)d_in[3];
    const float* W1  = (const float*)d_in[4];
    const float* b1  = (const float*)d_in[5];
    const float* g1  = (const float*)d_in[6];
    const float* be1 = (const float*)d_in[7];
    const float* rm1 = (const float*)d_in[8];
    const float* rv1 = (const float*)d_in[9];
    const float* W2  = (const float*)d_in[10];
    const float* b2  = (const float*)d_in[11];
    const float* g2  = (const float*)d_in[12];
    const float* be2 = (const float*)d_in[13];
    const float* rm2 = (const float*)d_in[14];
    const float* rv2 = (const float*)d_in[15];
    const float* cW1  = (const float*)d_in[16];
    const float* cb1  = (const float*)d_in[17];
    const float* cg1  = (const float*)d_in[18];
    const float* cbe1 = (const float*)d_in[19];
    const float* crm1 = (const float*)d_in[20];
    const float* crv1 = (const float*)d_in[21];
    const float* cW2  = (const float*)d_in[22];
    const float* cb2  = (const float*)d_in[23];
    const float* cg2  = (const float*)d_in[24];
    const float* cbe2 = (const float*)d_in[25];
    const float* crm2 = (const float*)d_in[26];
    const float* crv2 = (const float*)d_in[27];
    const float* cW3  = (const float*)d_in[28];
    const float* cb3  = (const float*)d_in[29];

    int DIN = in_sizes[4] / H;          // 128
    int N   = in_sizes[0] / DIN;        // 100000
    int E   = in_sizes[2];              // 1600000
    int B   = (out_size % (2 + H) == 0) ? out_size / (2 + H) : BCAP;  // 256

    const int* src = ei;
    const int* dst = ei + E;

    float *bufA, *bufC, *emb, *z1, *z2;
    cudaGetSymbolAddress((void**)&bufA, g_bufA);
    cudaGetSymbolAddress((void**)&bufC, g_bufC);
    cudaGetSymbolAddress((void**)&emb,  g_emb);
    cudaGetSymbolAddress((void**)&z1,   g_z1);
    cudaGetSymbolAddress((void**)&z2,   g_z2);

    float* out = (float*)d_out;

    int zt = N + B + B * H;
    k_zero<<<(zt + 255) / 256, 256>>>(N, B);
    k_deg<<<2048, 256>>>(dst, ew, E);
    k_prep<<<512, 256>>>(batch, N);

    // layer 1
    dim3 gg1(H / 64, (N + 63) / 64);
    k_gemm<<<gg1, 256>>>(x, W1, bufA, N, DIN, H);
    k_scatter<<<2368, 256>>>(bufA, src, dst, ew, E);
    k_final1<<<N, H>>>(bufA, bufC, b1, g1, be1, rm1, rv1);

    // layer 2
    dim3 gg2(H / 64, (N + 63) / 64);
    k_gemm<<<gg2, 256>>>(bufC, W2, bufA, N, H, H);
    k_scatter<<<2368, 256>>>(bufA, src, dst, ew, E);
    k_final2<<<N, H>>>(bufA, bufC, batch, b2, g2, be2, rm2, rv2);

    // pooling + classifier
    k_emb<<<(B * H + 255) / 256, 256>>>(out, out_size, B);
    k_mlp<<<B, 256, H * sizeof(float)>>>(emb, cW1, cb1, cg1, cbe1, crm1, crv1, z1, H, 256);
    k_mlp<<<B, 256, 256 * sizeof(float)>>>(z1, cW2, cb2, cg2, cbe2, crm2, crv2, z2, 256, 128);
    k_logits<<<(B * 2 + 255) / 256, 256>>>(cW3, cb3, out, B);
}

// round 4
// speedup vs baseline: 2.3684x; 2.3684x over previous
#include <cuda_runtime.h>
#include <cstddef>

#define H 256
#define NCAP 100000
#define ECAP 1600000
#define BCAP 256
#define BN_EPS 1e-5f

// ---------------- scratch (static __device__, allocation-free) ----------------
__device__ float g_bufA[(size_t)NCAP * H];   // GEMM output h' = h * dinv[row]
__device__ float g_bufC[(size_t)NCAP * H];   // h1 (post relu/bn) = residual
__device__ float g_wdeg[NCAP];               // weighted degree (float)
__device__ int   g_count[NCAP];              // edge count per dst
__device__ int   g_rowptr[NCAP + 1];
__device__ int   g_fill[NCAP];
__device__ int   g_csrc[ECAP];               // CSR: src node per edge slot
__device__ float g_cw[ECAP];                 // CSR: edge weight per slot
__device__ float g_dinv[NCAP];
__device__ float g_cnt[BCAP];
__device__ float g_pool[BCAP * H];
__device__ float g_emb[BCAP * H];
__device__ float g_z1[BCAP * 256];
__device__ float g_z2[BCAP * 128];
__device__ float g_bnA1[H], g_bnB1[H], g_bnA2[H], g_bnB2[H];

__device__ __forceinline__ void red_add_v4(float* addr, float x, float y, float z, float w) {
    asm volatile("red.global.add.v4.f32 [%0], {%1, %2, %3, %4};"
                 :: "l"(addr), "f"(x), "f"(y), "f"(z), "f"(w) : "memory");
}

// ---------------- zero accumulators ----------------
__global__ void k_zero(int n_nodes, int nb) {
    int total = 2 * n_nodes + nb + nb * H;
    for (int i = blockIdx.x * blockDim.x + threadIdx.x; i < total;
         i += gridDim.x * blockDim.x) {
        if (i < n_nodes) { g_wdeg[i] = 0.f; }
        else if (i < 2 * n_nodes) { g_count[i - n_nodes] = 0; }
        else if (i < 2 * n_nodes + nb) { g_cnt[i - 2 * n_nodes] = 0.f; }
        else { g_pool[i - 2 * n_nodes - nb] = 0.f; }
    }
}

// ---------------- histogram: count + weighted degree per dst ----------------
__global__ void k_hist(const int* __restrict__ dst, const float* __restrict__ ew, int E) {
    for (int e = blockIdx.x * blockDim.x + threadIdx.x; e < E;
         e += gridDim.x * blockDim.x) {
        int d = dst[e];
        atomicAdd(&g_count[d], 1);
        atomicAdd(&g_wdeg[d], ew[e]);
    }
}

// ---------------- dinv + per-graph node counts ----------------
__global__ void k_prep(const int* __restrict__ batch, int n_nodes) {
    for (int i = blockIdx.x * blockDim.x + threadIdx.x; i < n_nodes;
         i += gridDim.x * blockDim.x) {
        g_dinv[i] = rsqrtf(g_wdeg[i] + 1.0f);
        atomicAdd(&g_cnt[batch[i]], 1.0f);
    }
}

// ---------------- fold BN params: out = A*x + B (bias folded in) ----------------
__global__ void k_bnprep(const float* b1, const float* g1, const float* be1,
                         const float* rm1, const float* rv1,
                         const float* b2, const float* g2, const float* be2,
                         const float* rm2, const float* rv2) {
    int c = threadIdx.x;
    {
        float A = g1[c] * rsqrtf(rv1[c] + BN_EPS);
        g_bnA1[c] = A;
        g_bnB1[c] = be1[c] + (b1[c] - rm1[c]) * A;
    }
    {
        float A = g2[c] * rsqrtf(rv2[c] + BN_EPS);
        g_bnA2[c] = A;
        g_bnB2[c] = be2[c] + (b2[c] - rm2[c]) * A;
    }
}

// ---------------- single-block exclusive scan of g_count -> g_rowptr/g_fill ----------------
// 1024 threads, 4 elements per thread per chunk (4096/iter).
__global__ void k_scan(int N) {
    __shared__ int warp_sums[32];
    __shared__ int s_carry;
    int t = threadIdx.x, lane = t & 31, w = t >> 5;
    if (t == 0) s_carry = 0;
    __syncthreads();
    for (int base = 0; base < N; base += 4096) {
        int i0 = base + t * 4;
        int v[4];
        #pragma unroll
        for (int j = 0; j < 4; j++) v[j] = (i0 + j < N) ? g_count[i0 + j] : 0;
        int s = v[0] + v[1] + v[2] + v[3];
        // inclusive scan of s across block
        int x = s;
        #pragma unroll
        for (int o = 1; o < 32; o <<= 1) {
            int y = __shfl_up_sync(0xffffffffu, x, o);
            if (lane >= o) x += y;
        }
        if (lane == 31) warp_sums[w] = x;
        __syncthreads();
        if (w == 0) {
            int ws = warp_sums[lane];
            #pragma unroll
            for (int o = 1; o < 32; o <<= 1) {
                int y = __shfl_up_sync(0xffffffffu, ws, o);
                if (lane >= o) ws += y;
            }
            warp_sums[lane] = ws;
        }
        __syncthreads();
        int excl = x - s + (w > 0 ? warp_sums[w - 1] : 0) + s_carry;
        #pragma unroll
        for (int j = 0; j < 4; j++) {
            if (i0 + j < N) { g_rowptr[i0 + j] = excl; g_fill[i0 + j] = excl; }
            excl += v[j];
        }
        __syncthreads();
        if (t == 1023) s_carry = excl;
        __syncthreads();
    }
    if (t == 0) g_rowptr[N] = s_carry;
}

// ---------------- scatter edges into CSR slots ----------------
__global__ void k_build(const int* __restrict__ src, const int* __restrict__ dst,
                        const float* __restrict__ ew, int E) {
    for (int e = blockIdx.x * blockDim.x + threadIdx.x; e < E;
         e += gridDim.x * blockDim.x) {
        int d = dst[e];
        int p = atomicAdd(&g_fill[d], 1);
        g_csrc[p] = src[e];
        g_cw[p] = ew[e];
    }
}

// ---------------- fp32 GEMM: C[r,c] = (A[M,K] @ W[K,Nc])[r,c] * scale[r] ----------------
// 128x64 tile, BK=16, 256 threads, 8x4 per thread.
__global__ void k_gemm(const float* __restrict__ A, const float* __restrict__ W,
                       float* __restrict__ C, const float* __restrict__ scale,
                       int M, int K, int Nc) {
    __shared__ float As[16][132];   // transposed, padded (132 = mult of 4)
    __shared__ float Bs[16][64];

    int t = threadIdx.x;
    int tx = t & 15, ty = t >> 4;
    int row0 = blockIdx.y * 128;
    int col0 = blockIdx.x * 64;

    int ar = t >> 2;          // 0..63
    int akq = (t & 3) * 4;    // 0,4,8,12
    int brow = t >> 4;        // 0..15
    int bc = (t & 15) * 4;    // 0..60

    float acc[8][4] = {};

    for (int k0 = 0; k0 < K; k0 += 16) {
        #pragma unroll
        for (int h = 0; h < 2; h++) {
            int r = ar + h * 64;
            int gr = row0 + r;
            float4 av = make_float4(0.f, 0.f, 0.f, 0.f);
            if (gr < M) av = *(const float4*)(A + (size_t)gr * K + k0 + akq);
            As[akq + 0][r] = av.x;
            As[akq + 1][r] = av.y;
            As[akq + 2][r] = av.z;
            As[akq + 3][r] = av.w;
        }
        *(float4*)&Bs[brow][bc] = *(const float4*)(W + (size_t)(k0 + brow) * Nc + col0 + bc);
        __syncthreads();

        #pragma unroll
        for (int k = 0; k < 16; k++) {
            float4 a0 = *(const float4*)&As[k][ty * 8];
            float4 a1 = *(const float4*)&As[k][ty * 8 + 4];
            float4 b4 = *(const float4*)&Bs[k][tx * 4];
            float a[8] = {a0.x, a0.y, a0.z, a0.w, a1.x, a1.y, a1.z, a1.w};
            float b[4] = {b4.x, b4.y, b4.z, b4.w};
            #pragma unroll
            for (int i = 0; i < 8; i++)
                #pragma unroll
                for (int j = 0; j < 4; j++)
                    acc[i][j] += a[i] * b[j];
        }
        __syncthreads();
    }

    #pragma unroll
    for (int i = 0; i < 8; i++) {
        int gr = row0 + ty * 8 + i;
        if (gr < M) {
            float s = scale[gr];
            float4 o = make_float4(acc[i][0] * s, acc[i][1] * s, acc[i][2] * s, acc[i][3] * s);
            *(float4*)(C + (size_t)gr * Nc + col0 + tx * 4) = o;
        }
    }
}

// ---------------- CSR gather layer 1: out = relu(bnA*(dinv[d]*acc) + bnB) ----------------
// acc = h'[d] + sum_e cw[e]*h'[csrc[e]];  64 threads/node, float4 lanes.
__global__ void k_gather1(const float* __restrict__ hp, float* __restrict__ out, int N) {
    int lane = threadIdx.x & 63;
    int d = blockIdx.x * 4 + (threadIdx.x >> 6);
    if (d >= N) return;
    int c = lane * 4;
    int beg = __ldg(&g_rowptr[d]), end = __ldg(&g_rowptr[d + 1]);

    float4 acc = *(const float4*)(hp + (size_t)d * H + c);  // self-loop term
    for (int e = beg; e < end; e++) {
        int s = __ldg(&g_csrc[e]);
        float w = __ldg(&g_cw[e]);
        float4 v = *(const float4*)(hp + (size_t)s * H + c);
        acc.x += w * v.x; acc.y += w * v.y; acc.z += w * v.z; acc.w += w * v.w;
    }
    float di = g_dinv[d];
    float4 A = *(const float4*)&g_bnA1[c];
    float4 Bv = *(const float4*)&g_bnB1[c];
    float4 o;
    o.x = fmaxf(A.x * (di * acc.x) + Bv.x, 0.f);
    o.y = fmaxf(A.y * (di * acc.y) + Bv.y, 0.f);
    o.z = fmaxf(A.z * (di * acc.z) + Bv.z, 0.f);
    o.w = fmaxf(A.w * (di * acc.w) + Bv.w, 0.f);
    *(float4*)(out + (size_t)d * H + c) = o;
}

// ---------------- CSR gather layer 2 + residual + pool accumulate ----------------
__global__ void k_gather2(const float* __restrict__ hp, const float* __restrict__ res,
                          const int* __restrict__ batch, int N) {
    int lane = threadIdx.x & 63;
    int d = blockIdx.x * 4 + (threadIdx.x >> 6);
    if (d >= N) return;
    int c = lane * 4;
    int beg = __ldg(&g_rowptr[d]), end = __ldg(&g_rowptr[d + 1]);

    float4 acc = *(const float4*)(hp + (size_t)d * H + c);
    for (int e = beg; e < end; e++) {
        int s = __ldg(&g_csrc[e]);
        float w = __ldg(&g_cw[e]);
        float4 v = *(const float4*)(hp + (size_t)s * H + c);
        acc.x += w * v.x; acc.y += w * v.y; acc.z += w * v.z; acc.w += w * v.w;
    }
    float di = g_dinv[d];
    float4 A = *(const float4*)&g_bnA2[c];
    float4 Bv = *(const float4*)&g_bnB2[c];
    float4 r = *(const float4*)(res + (size_t)d * H + c);
    float vx = fmaxf(A.x * (di * acc.x) + Bv.x, 0.f) + r.x;
    float vy = fmaxf(A.y * (di * acc.y) + Bv.y, 0.f) + r.y;
    float vz = fmaxf(A.z * (di * acc.z) + Bv.z, 0.f) + r.z;
    float vw = fmaxf(A.w * (di * acc.w) + Bv.w, 0.f) + r.w;
    int b = __ldg(&batch[d]);
    red_add_v4(&g_pool[(size_t)b * H + c], vx, vy, vz, vw);
}

// ---------------- per-graph mean + write emb output ----------------
__global__ void k_emb(float* __restrict__ out, int out_size, int nb) {
    int i = blockIdx.x * blockDim.x + threadIdx.x;
    if (i < nb * H) {
        int b = i >> 8;
        float e = g_pool[i] / fmaxf(g_cnt[b], 1.0f);
        g_emb[i] = e;
        if (out_size >= nb * 2 + nb * H)
            out[nb * 2 + i] = e;
    }
}

// ---------------- classifier MLP layer: out = relu(bn(in @ W + b)) ----------------
__global__ void k_mlp(const float* __restrict__ in, const float* __restrict__ W,
                      const float* __restrict__ bb, const float* __restrict__ gg,
                      const float* __restrict__ be, const float* __restrict__ rm,
                      const float* __restrict__ rv, float* __restrict__ out,
                      int Kin, int Nout) {
    extern __shared__ float sh[];
    int b = blockIdx.x, t = threadIdx.x;
    for (int k = t; k < Kin; k += blockDim.x) sh[k] = in[(size_t)b * Kin + k];
    __syncthreads();
    if (t < Nout) {
        float acc = 0.f;
        for (int k = 0; k < Kin; k++) acc += sh[k] * W[(size_t)k * Nout + t];
        acc += bb[t];
        acc = (acc - rm[t]) * rsqrtf(rv[t] + BN_EPS) * gg[t] + be[t];
        out[(size_t)b * Nout + t] = fmaxf(acc, 0.f);
    }
}

// ---------------- final logits ----------------
__global__ void k_logits(const float* __restrict__ W, const float* __restrict__ bb,
                         float* __restrict__ out, int nb) {
    int i = blockIdx.x * blockDim.x + threadIdx.x;
    if (i < nb * 2) {
        int b = i >> 1, o = i & 1;
        float acc = bb[o];
        for (int k = 0; k < 128; k++) acc += g_z2[b * 128 + k] * W[k * 2 + o];
        out[i] = acc;
    }
}

extern "C" void kernel_launch(void* const* d_in, const int* in_sizes, int n_in,
                              void* d_out, int out_size) {
    const float* x     = (const float*)d_in[0];
    const int*   ei    = (const int*)d_in[1];
    const float* ew    = (const float*)d_in[2];
    const int*   batch = (const int*)d_in[3];
    const float* W1  = (const float*)d_in[4];
    const float* b1  = (const float*)d_in[5];
    const float* g1  = (const float*)d_in[6];
    const float* be1 = (const float*)d_in[7];
    const float* rm1 = (const float*)d_in[8];
    const float* rv1 = (const float*)d_in[9];
    const float* W2  = (const float*)d_in[10];
    const float* b2  = (const float*)d_in[11];
    const float* g2  = (const float*)d_in[12];
    const float* be2 = (const float*)d_in[13];
    const float* rm2 = (const float*)d_in[14];
    const float* rv2 = (const float*)d_in[15];
    const float* cW1  = (const float*)d_in[16];
    const float* cb1  = (const float*)d_in[17];
    const float* cg1  = (const float*)d_in[18];
    const float* cbe1 = (const float*)d_in[19];
    const float* crm1 = (const float*)d_in[20];
    const float* crv1 = (const float*)d_in[21];
    const float* cW2  = (const float*)d_in[22];
    const float* cb2  = (const float*)d_in[23];
    const float* cg2  = (const float*)d_in[24];
    const float* cbe2 = (const float*)d_in[25];
    const float* crm2 = (const float*)d_in[26];
    const float* crv2 = (const float*)d_in[27];
    const float* cW3  = (const float*)d_in[28];
    const float* cb3  = (const float*)d_in[29];

    int DIN = in_sizes[4] / H;          // 128
    int N   = in_sizes[0] / DIN;        // 100000
    int E   = in_sizes[2];              // 1600000
    int B   = (out_size % (2 + H) == 0) ? out_size / (2 + H) : BCAP;  // 256

    const int* src = ei;
    const int* dst = ei + E;

    float *bufA, *bufC, *emb, *z1, *z2, *dinv;
    cudaGetSymbolAddress((void**)&bufA, g_bufA);
    cudaGetSymbolAddress((void**)&bufC, g_bufC);
    cudaGetSymbolAddress((void**)&emb,  g_emb);
    cudaGetSymbolAddress((void**)&z1,   g_z1);
    cudaGetSymbolAddress((void**)&z2,   g_z2);
    cudaGetSymbolAddress((void**)&dinv, g_dinv);

    float* out = (float*)d_out;

    // prep: histogram, dinv, BN fold, CSR build
    int zt = 2 * N + B + B * H;
    k_zero<<<(zt + 255) / 256, 256>>>(N, B);
    k_hist<<<2048, 256>>>(dst, ew, E);
    k_prep<<<512, 256>>>(batch, N);
    k_bnprep<<<1, H>>>(b1, g1, be1, rm1, rv1, b2, g2, be2, rm2, rv2);
    k_scan<<<1, 1024>>>(N);
    k_build<<<2048, 256>>>(src, dst, ew, E);

    // layer 1
    dim3 gg1(H / 64, (N + 127) / 128);
    k_gemm<<<gg1, 256>>>(x, W1, bufA, dinv, N, DIN, H);
    k_gather1<<<(N + 3) / 4, 256>>>(bufA, bufC, N);

    // layer 2
    k_gemm<<<gg1, 256>>>(bufC, W2, bufA, dinv, N, H, H);
    k_gather2<<<(N + 3) / 4, 256>>>(bufA, bufC, batch, N);

    // pooling + classifier
    k_emb<<<(B * H + 255) / 256, 256>>>(out, out_size, B);
    k_mlp<<<B, 256, H * sizeof(float)>>>(emb, cW1, cb1, cg1, cbe1, crm1, crv1, z1, H, 256);
    k_mlp<<<B, 256, 256 * sizeof(float)>>>(z1, cW2, cb2, cg2, cbe2, crm2, crv2, z2, 256, 128);
    k_logits<<<(B * 2 + 255) / 256, 256>>>(cW3, cb3, out, B);
}